// round 12
// baseline (speedup 1.0000x reference)
#include <cuda_runtime.h>
#include <cuda_fp16.h>
#include <cstdint>

#define N_NODES 50000
#define N_EDGES 800000
#define IN_DIM 128
#define OUT_DIM 64
#define NUM_HEADS 4
#define MAXDEG 96

// Scratch (no cudaMalloc allowed)
__device__ float  g_Whi[IN_DIM * OUT_DIM];           // tf32-rounded hi part of Wavg
__device__ float  g_Wlo[IN_DIM * OUT_DIM];           // tf32-rounded residual
__device__ __half g_hph[N_NODES * OUT_DIM];          // 6.4 MB projected features (fp16)
__device__ int    g_deg[N_NODES];                    // statically zero-initialized
__device__ int    g_adj[(size_t)N_NODES * MAXDEG];   // 19.2 MB

// ---------------------------------------------------------------------------
// tf32 helpers
// ---------------------------------------------------------------------------
__device__ __forceinline__ void split_tf32(float x, uint32_t& hi, uint32_t& lo) {
    asm("cvt.rna.tf32.f32 %0, %1;" : "=r"(hi) : "f"(x));
    float r = x - __uint_as_float(hi);
    asm("cvt.rna.tf32.f32 %0, %1;" : "=r"(lo) : "f"(r));
}

#define MMA_TF32(D, A0, A1, A2, A3, B0, B1)                                    \
    asm("mma.sync.aligned.m16n8k8.row.col.f32.tf32.tf32.f32 "                  \
        "{%0,%1,%2,%3}, {%4,%5,%6,%7}, {%8,%9}, {%0,%1,%2,%3};"                \
        : "+f"((D)[0]), "+f"((D)[1]), "+f"((D)[2]), "+f"((D)[3])               \
        : "r"(A0), "r"(A1), "r"(A2), "r"(A3), "r"(B0), "r"(B1))

// ---------------------------------------------------------------------------
// Kernel 1: setup — Wavg tf32 hi/lo split only (deg zeroing handled by
// pull_kernel's per-node reset; g_deg is zero at module load).
// ---------------------------------------------------------------------------
__global__ void setup_kernel(const float* __restrict__ W) {
    int i = blockIdx.x * blockDim.x + threadIdx.x;
    if (i < IN_DIM * OUT_DIM) {
        float avg = 0.25f * (W[i] + W[IN_DIM * OUT_DIM + i] +
                             W[2 * IN_DIM * OUT_DIM + i] + W[3 * IN_DIM * OUT_DIM + i]);
        uint32_t hi, lo;
        split_tf32(avg, hi, lo);
        g_Whi[i] = __uint_as_float(hi);
        g_Wlo[i] = __uint_as_float(lo);
    }
}

// ---------------------------------------------------------------------------
// Kernel 2: FUSED heterogeneous kernel.
//   bid % 3 == 0  -> GEMM tile (hp = h @ Wavg via 3xTF32 mma)   [391 blocks]
//   otherwise     -> adjacency-build chunk (4 edges/thread)      [782 blocks]
// ---------------------------------------------------------------------------
#define BM 128
#define KPH 64
#define PA 68     // sA pitch in floats -> fragment bank = (4*gID + tig) % 32, all distinct

__global__ __launch_bounds__(256) void fused_kernel(const float* __restrict__ h,
                                                    const int* __restrict__ src,
                                                    const int* __restrict__ dst,
                                                    int n_nodes, int n_edges,
                                                    int n_gemm_blocks) {
    __shared__ float sA[BM * PA];    // ~34.8 KB (used by GEMM role)

    int bid = blockIdx.x;
    int tid = threadIdx.x;

    if (bid % 3 != 0 || bid / 3 >= n_gemm_blocks) {
        // ---------------- adjacency role ----------------
        int adjId = bid - bid / 3 - 1;
        if (bid % 3 == 0) adjId = bid;
        int g = adjId * 256 + tid;               // edge group (4 edges)
        int nG = n_edges >> 2;
        if (g < nG) {
            int4 s = ((const int4*)src)[g];
            int4 d = ((const int4*)dst)[g];
            int p0 = atomicAdd(&g_deg[d.x], 1);
            int p1 = atomicAdd(&g_deg[d.y], 1);
            int p2 = atomicAdd(&g_deg[d.z], 1);
            int p3 = atomicAdd(&g_deg[d.w], 1);
            if (p0 < MAXDEG) g_adj[(size_t)d.x * MAXDEG + p0] = s.x;
            if (p1 < MAXDEG) g_adj[(size_t)d.y * MAXDEG + p1] = s.y;
            if (p2 < MAXDEG) g_adj[(size_t)d.z * MAXDEG + p2] = s.z;
            if (p3 < MAXDEG) g_adj[(size_t)d.w * MAXDEG + p3] = s.w;
        } else if (g == nG) {
            for (int e = nG * 4; e < n_edges; e++) {
                int d = dst[e];
                int pos = atomicAdd(&g_deg[d], 1);
                if (pos < MAXDEG) g_adj[(size_t)d * MAXDEG + pos] = src[e];
            }
        }
        return;
    }

    // ---------------- GEMM role ----------------
    int tile = bid / 3;
    int lane = tid & 31;
    int wid  = tid >> 5;       // 0..7
    int wm   = wid & 3;        // M strip: rows wm*32..wm*32+31
    int wn   = wid >> 2;       // N strip: cols wn*32..wn*32+31
    int gID  = lane >> 2;      // 0..7
    int tig  = lane & 3;       // 0..3
    int rowBase = tile * BM;

    float d[2][4][4];          // [mtile][ntile][frag]
    #pragma unroll
    for (int mt = 0; mt < 2; mt++)
        #pragma unroll
        for (int nt = 0; nt < 4; nt++)
            #pragma unroll
            for (int q = 0; q < 4; q++) d[mt][nt][q] = 0.f;

    #pragma unroll
    for (int ph = 0; ph < 2; ph++) {
        // stage h slab: 128 rows x 64 floats = 2048 float4, 8 per thread
        #pragma unroll
        for (int it = 0; it < 8; it++) {
            int item = tid + it * 256;
            int r = item >> 4;          // 16 float4 per row
            int c = item & 15;
            int row = rowBase + r;
            float4 v = make_float4(0.f, 0.f, 0.f, 0.f);
            if (row < n_nodes)
                v = ((const float4*)(h + (size_t)row * IN_DIM + ph * KPH))[c];
            *(float4*)(sA + r * PA + 4 * c) = v;
        }
        __syncthreads();

        #pragma unroll
        for (int kk = 0; kk < KPH; kk += 8) {
            int kg = ph * KPH + kk + tig;    // global k of b0 row

            // B fragments hi/lo for 4 n-tiles (L1-resident __ldg)
            uint32_t bhi[4][2], blo[4][2];
            #pragma unroll
            for (int nt = 0; nt < 4; nt++) {
                int ncol = wn * 32 + nt * 8 + gID;
                int i0 = kg * OUT_DIM + ncol;
                int i1 = (kg + 4) * OUT_DIM + ncol;
                bhi[nt][0] = __float_as_uint(__ldg(g_Whi + i0));
                bhi[nt][1] = __float_as_uint(__ldg(g_Whi + i1));
                blo[nt][0] = __float_as_uint(__ldg(g_Wlo + i0));
                blo[nt][1] = __float_as_uint(__ldg(g_Wlo + i1));
            }

            #pragma unroll
            for (int mt = 0; mt < 2; mt++) {
                const float* ab = sA + (wm * 32 + mt * 16 + gID) * PA + kk + tig;
                float a0 = ab[0];
                float a1 = ab[8 * PA];
                float a2 = ab[4];
                float a3 = ab[8 * PA + 4];
                uint32_t ah[4], al[4];
                split_tf32(a0, ah[0], al[0]);
                split_tf32(a1, ah[1], al[1]);
                split_tf32(a2, ah[2], al[2]);
                split_tf32(a3, ah[3], al[3]);

                #pragma unroll
                for (int nt = 0; nt < 4; nt++) {
                    MMA_TF32(d[mt][nt], ah[0], ah[1], ah[2], ah[3],
                             bhi[nt][0], bhi[nt][1]);
                    MMA_TF32(d[mt][nt], al[0], al[1], al[2], al[3],
                             bhi[nt][0], bhi[nt][1]);
                    MMA_TF32(d[mt][nt], ah[0], ah[1], ah[2], ah[3],
                             blo[nt][0], blo[nt][1]);
                }
            }
        }
        __syncthreads();
    }

    // epilogue: fp16 stores (half2 per fragment pair)
    #pragma unroll
    for (int mt = 0; mt < 2; mt++) {
        int r0 = rowBase + wm * 32 + mt * 16 + gID;
        #pragma unroll
        for (int nt = 0; nt < 4; nt++) {
            int col = wn * 32 + nt * 8 + tig * 2;
            if (r0 < n_nodes)
                *(__half2*)(g_hph + (size_t)r0 * OUT_DIM + col) =
                    __floats2half2_rn(d[mt][nt][0], d[mt][nt][1]);
            if (r0 + 8 < n_nodes)
                *(__half2*)(g_hph + (size_t)(r0 + 8) * OUT_DIM + col) =
                    __floats2half2_rn(d[mt][nt][2], d[mt][nt][3]);
        }
    }
}

// ---------------------------------------------------------------------------
// Kernel 3: pull-aggregate + bias + relu (fp16 gathers, fp32 accumulation).
// 16 threads per dst node, each owns 4 half columns (8B uint2 loads).
// Resets g_deg[node] to 0 afterwards so the next graph replay starts clean.
// ---------------------------------------------------------------------------
__global__ __launch_bounds__(256) void pull_kernel(const float* __restrict__ b,
                                                   float* __restrict__ out,
                                                   int n_nodes) {
    unsigned int t = blockIdx.x * blockDim.x + threadIdx.x;
    unsigned int node = t >> 4;
    if (node >= (unsigned int)n_nodes) return;
    int c4 = (t & 15) * 4;    // half-column offset

    int deg = g_deg[node];
    __syncwarp();
    if ((t & 15) == 0) g_deg[node] = 0;    // reset for next replay
    if (deg > MAXDEG) deg = MAXDEG;
    const int* adj = g_adj + (size_t)node * MAXDEG;

    float2 accA = make_float2(0.f, 0.f);
    float2 accB = make_float2(0.f, 0.f);

    #define GATHER(sv)                                                         \
        {                                                                      \
            uint2 u = *(const uint2*)(g_hph + (size_t)(sv) * OUT_DIM + c4);    \
            float2 f0 = __half22float2(*(__half2*)&u.x);                       \
            float2 f1 = __half22float2(*(__half2*)&u.y);                       \
            accA.x += f0.x; accA.y += f0.y;                                    \
            accB.x += f1.x; accB.y += f1.y;                                    \
        }

    int e = 0;
    for (; e + 8 <= deg; e += 8) {
        int s0 = __ldg(adj + e + 0);
        int s1 = __ldg(adj + e + 1);
        int s2 = __ldg(adj + e + 2);
        int s3 = __ldg(adj + e + 3);
        int s4 = __ldg(adj + e + 4);
        int s5 = __ldg(adj + e + 5);
        int s6 = __ldg(adj + e + 6);
        int s7 = __ldg(adj + e + 7);
        GATHER(s0); GATHER(s1); GATHER(s2); GATHER(s3);
        GATHER(s4); GATHER(s5); GATHER(s6); GATHER(s7);
    }
    for (; e < deg; e++) {
        int s = __ldg(adj + e);
        GATHER(s);
    }
    #undef GATHER

    float4 bb = *(const float4*)(b + c4);
    float4 r;
    r.x = fmaxf(accA.x + bb.x, 0.f);
    r.y = fmaxf(accA.y + bb.y, 0.f);
    r.z = fmaxf(accB.x + bb.z, 0.f);
    r.w = fmaxf(accB.y + bb.w, 0.f);
    *(float4*)(out + (size_t)node * OUT_DIM + c4) = r;
}

// ---------------------------------------------------------------------------
// Launch
// inputs: 0=h [N,128] f32, 1=W [4,128,64] f32, 2=b [64] f32,
//         3=src [E] i32, 4=dst [E] i32 ; out: [N,64] f32
// ---------------------------------------------------------------------------
extern "C" void kernel_launch(void* const* d_in, const int* in_sizes, int n_in,
                              void* d_out, int out_size) {
    const float* h   = (const float*)d_in[0];
    const float* W   = (const float*)d_in[1];
    const float* b   = (const float*)d_in[2];
    const int*   src = (const int*)d_in[3];
    const int*   dst = (const int*)d_in[4];
    float* out = (float*)d_out;

    int n_nodes = in_sizes[0] / IN_DIM;    // 50000
    int n_edges = in_sizes[3];             // 800000

    // 1. setup: Wavg tf32 split
    setup_kernel<<<(IN_DIM * OUT_DIM + 255) / 256, 256>>>(W);

    // 2. fused GEMM + adjacency build
    {
        int n_gemm = (n_nodes + BM - 1) / BM;                 // 391
        int nGroups = n_edges / 4 + 1;                        // 200001
        int n_adj = (nGroups + 255) / 256;                    // 782
        int grid = 3 * n_gemm;                                // 391 gemm, 782 adj
        if (grid - n_gemm < n_adj) grid = n_gemm + n_adj + (n_gemm + n_adj) / 2 + 2;
        fused_kernel<<<grid, 256>>>(h, src, dst, n_nodes, n_edges, n_gemm);
    }

    // 3. pull-aggregate + bias + relu
    {
        long long threads = (long long)n_nodes * 16;
        int blocks = (int)((threads + 255) / 256);
        pull_kernel<<<blocks, 256>>>(b, out, n_nodes);
    }
}

// round 13
// speedup vs baseline: 1.3894x; 1.3894x over previous
#include <cuda_runtime.h>
#include <cuda_bf16.h>
#include <cstdint>

#define N_NODES 50000
#define N_EDGES 800000
#define IN_DIM 128
#define OUT_DIM 64
#define NUM_HEADS 4
#define MAXDEG 96

// Scratch (no cudaMalloc allowed)
__device__ float g_Whi[IN_DIM * OUT_DIM];           // tf32-rounded hi part of Wavg
__device__ float g_Wlo[IN_DIM * OUT_DIM];           // tf32-rounded residual
__device__ float g_hp[N_NODES * OUT_DIM];           // 12.8 MB
__device__ int   g_deg[N_NODES];                    // 200 KB
__device__ int   g_adj[(size_t)N_NODES * MAXDEG];   // 19.2 MB

// ---------------------------------------------------------------------------
// tf32 helpers
// ---------------------------------------------------------------------------
__device__ __forceinline__ void split_tf32(float x, uint32_t& hi, uint32_t& lo) {
    asm("cvt.rna.tf32.f32 %0, %1;" : "=r"(hi) : "f"(x));
    float r = x - __uint_as_float(hi);
    asm("cvt.rna.tf32.f32 %0, %1;" : "=r"(lo) : "f"(r));
}

#define MMA_TF32(D, A0, A1, A2, A3, B0, B1)                                    \
    asm("mma.sync.aligned.m16n8k8.row.col.f32.tf32.tf32.f32 "                  \
        "{%0,%1,%2,%3}, {%4,%5,%6,%7}, {%8,%9}, {%0,%1,%2,%3};"                \
        : "+f"((D)[0]), "+f"((D)[1]), "+f"((D)[2]), "+f"((D)[3])               \
        : "r"(A0), "r"(A1), "r"(A2), "r"(A3), "r"(B0), "r"(B1))

// ---------------------------------------------------------------------------
// Kernel 1: setup — Wavg tf32 hi/lo split + zero degree counters
// ---------------------------------------------------------------------------
__global__ void setup_kernel(const float* __restrict__ W, int n_nodes) {
    int i = blockIdx.x * blockDim.x + threadIdx.x;
    if (i < IN_DIM * OUT_DIM) {
        float avg = 0.25f * (W[i] + W[IN_DIM * OUT_DIM + i] +
                             W[2 * IN_DIM * OUT_DIM + i] + W[3 * IN_DIM * OUT_DIM + i]);
        uint32_t hi, lo;
        split_tf32(avg, hi, lo);
        g_Whi[i] = __uint_as_float(hi);
        g_Wlo[i] = __uint_as_float(lo);
    }
    // zero deg (grid-stride over int4)
    int n4 = n_nodes >> 2;
    for (int j = i; j < n4; j += gridDim.x * blockDim.x)
        ((int4*)g_deg)[j] = make_int4(0, 0, 0, 0);
    if (i < (n_nodes & 3)) g_deg[n4 * 4 + i] = 0;
}

// ---------------------------------------------------------------------------
// Kernel 2: FUSED heterogeneous kernel.
//   bid % 3 == 0  -> GEMM tile (hp = h @ Wavg via 3xTF32 mma)   [391 blocks]
//   otherwise     -> adjacency-build chunk (4 edges/thread)      [782 blocks]
// launch_bounds (256, 3): cap regs at 85 so 3 CTAs/SM co-reside (was 2).
// ---------------------------------------------------------------------------
#define BM 128
#define KPH 64
#define PA 68     // sA pitch in floats -> fragment bank = (4*gID + tig) % 32, all distinct

__global__ __launch_bounds__(256, 3) void fused_kernel(const float* __restrict__ h,
                                                       const int* __restrict__ src,
                                                       const int* __restrict__ dst,
                                                       int n_nodes, int n_edges,
                                                       int n_gemm_blocks) {
    __shared__ float sA[BM * PA];    // ~34.8 KB (used by GEMM role)

    int bid = blockIdx.x;
    int tid = threadIdx.x;

    if (bid % 3 != 0 || bid / 3 >= n_gemm_blocks) {
        // ---------------- adjacency role ----------------
        int adjId = bid - bid / 3 - 1;
        if (bid % 3 == 0) adjId = bid;
        int g = adjId * 256 + tid;               // edge group (4 edges)
        int nG = n_edges >> 2;
        if (g < nG) {
            int4 s = ((const int4*)src)[g];
            int4 d = ((const int4*)dst)[g];
            int p0 = atomicAdd(&g_deg[d.x], 1);
            int p1 = atomicAdd(&g_deg[d.y], 1);
            int p2 = atomicAdd(&g_deg[d.z], 1);
            int p3 = atomicAdd(&g_deg[d.w], 1);
            if (p0 < MAXDEG) g_adj[(size_t)d.x * MAXDEG + p0] = s.x;
            if (p1 < MAXDEG) g_adj[(size_t)d.y * MAXDEG + p1] = s.y;
            if (p2 < MAXDEG) g_adj[(size_t)d.z * MAXDEG + p2] = s.z;
            if (p3 < MAXDEG) g_adj[(size_t)d.w * MAXDEG + p3] = s.w;
        } else if (g == nG) {
            for (int e = nG * 4; e < n_edges; e++) {
                int d = dst[e];
                int pos = atomicAdd(&g_deg[d], 1);
                if (pos < MAXDEG) g_adj[(size_t)d * MAXDEG + pos] = src[e];
            }
        }
        return;
    }

    // ---------------- GEMM role ----------------
    int tile = bid / 3;
    int lane = tid & 31;
    int wid  = tid >> 5;       // 0..7
    int wm   = wid & 3;        // M strip: rows wm*32..wm*32+31
    int wn   = wid >> 2;       // N strip: cols wn*32..wn*32+31
    int gID  = lane >> 2;      // 0..7
    int tig  = lane & 3;       // 0..3
    int rowBase = tile * BM;

    float d[2][4][4];          // [mtile][ntile][frag]
    #pragma unroll
    for (int mt = 0; mt < 2; mt++)
        #pragma unroll
        for (int nt = 0; nt < 4; nt++)
            #pragma unroll
            for (int q = 0; q < 4; q++) d[mt][nt][q] = 0.f;

    #pragma unroll
    for (int ph = 0; ph < 2; ph++) {
        // stage h slab: 128 rows x 64 floats = 2048 float4, 8 per thread
        #pragma unroll
        for (int it = 0; it < 8; it++) {
            int item = tid + it * 256;
            int r = item >> 4;          // 16 float4 per row
            int c = item & 15;
            int row = rowBase + r;
            float4 v = make_float4(0.f, 0.f, 0.f, 0.f);
            if (row < n_nodes)
                v = ((const float4*)(h + (size_t)row * IN_DIM + ph * KPH))[c];
            *(float4*)(sA + r * PA + 4 * c) = v;
        }
        __syncthreads();

        #pragma unroll
        for (int kk = 0; kk < KPH; kk += 8) {
            int kg = ph * KPH + kk + tig;    // global k of b0 row

            // B fragments hi/lo for 4 n-tiles (L1-resident __ldg)
            uint32_t bhi[4][2], blo[4][2];
            #pragma unroll
            for (int nt = 0; nt < 4; nt++) {
                int ncol = wn * 32 + nt * 8 + gID;
                int i0 = kg * OUT_DIM + ncol;
                int i1 = (kg + 4) * OUT_DIM + ncol;
                bhi[nt][0] = __float_as_uint(__ldg(g_Whi + i0));
                bhi[nt][1] = __float_as_uint(__ldg(g_Whi + i1));
                blo[nt][0] = __float_as_uint(__ldg(g_Wlo + i0));
                blo[nt][1] = __float_as_uint(__ldg(g_Wlo + i1));
            }

            #pragma unroll
            for (int mt = 0; mt < 2; mt++) {
                const float* ab = sA + (wm * 32 + mt * 16 + gID) * PA + kk + tig;
                float a0 = ab[0];
                float a1 = ab[8 * PA];
                float a2 = ab[4];
                float a3 = ab[8 * PA + 4];
                uint32_t ah[4], al[4];
                split_tf32(a0, ah[0], al[0]);
                split_tf32(a1, ah[1], al[1]);
                split_tf32(a2, ah[2], al[2]);
                split_tf32(a3, ah[3], al[3]);

                #pragma unroll
                for (int nt = 0; nt < 4; nt++) {
                    MMA_TF32(d[mt][nt], ah[0], ah[1], ah[2], ah[3],
                             bhi[nt][0], bhi[nt][1]);
                    MMA_TF32(d[mt][nt], al[0], al[1], al[2], al[3],
                             bhi[nt][0], bhi[nt][1]);
                    MMA_TF32(d[mt][nt], ah[0], ah[1], ah[2], ah[3],
                             blo[nt][0], blo[nt][1]);
                }
            }
        }
        __syncthreads();
    }

    // epilogue
    #pragma unroll
    for (int mt = 0; mt < 2; mt++) {
        int r0 = rowBase + wm * 32 + mt * 16 + gID;
        #pragma unroll
        for (int nt = 0; nt < 4; nt++) {
            int col = wn * 32 + nt * 8 + tig * 2;
            if (r0 < n_nodes)
                *(float2*)(g_hp + (size_t)r0 * OUT_DIM + col) =
                    make_float2(d[mt][nt][0], d[mt][nt][1]);
            if (r0 + 8 < n_nodes)
                *(float2*)(g_hp + (size_t)(r0 + 8) * OUT_DIM + col) =
                    make_float2(d[mt][nt][2], d[mt][nt][3]);
        }
    }
}

// ---------------------------------------------------------------------------
// Kernel 3: pull-aggregate + bias + relu.
// ---------------------------------------------------------------------------
__global__ __launch_bounds__(256) void pull_kernel(const float* __restrict__ b,
                                                   float* __restrict__ out,
                                                   int n_nodes) {
    unsigned int t = blockIdx.x * blockDim.x + threadIdx.x;
    unsigned int node = t >> 4;
    if (node >= (unsigned int)n_nodes) return;
    int c4 = (t & 15) * 4;

    int deg = g_deg[node];
    if (deg > MAXDEG) deg = MAXDEG;
    const int* adj = g_adj + (size_t)node * MAXDEG;

    float4 acc = make_float4(0.f, 0.f, 0.f, 0.f);
    int e = 0;
    for (; e + 8 <= deg; e += 8) {
        int s0 = __ldg(adj + e + 0);
        int s1 = __ldg(adj + e + 1);
        int s2 = __ldg(adj + e + 2);
        int s3 = __ldg(adj + e + 3);
        int s4 = __ldg(adj + e + 4);
        int s5 = __ldg(adj + e + 5);
        int s6 = __ldg(adj + e + 6);
        int s7 = __ldg(adj + e + 7);
        float4 v0 = *(const float4*)(g_hp + (size_t)s0 * OUT_DIM + c4);
        float4 v1 = *(const float4*)(g_hp + (size_t)s1 * OUT_DIM + c4);
        float4 v2 = *(const float4*)(g_hp + (size_t)s2 * OUT_DIM + c4);
        float4 v3 = *(const float4*)(g_hp + (size_t)s3 * OUT_DIM + c4);
        float4 v4 = *(const float4*)(g_hp + (size_t)s4 * OUT_DIM + c4);
        float4 v5 = *(const float4*)(g_hp + (size_t)s5 * OUT_DIM + c4);
        float4 v6 = *(const float4*)(g_hp + (size_t)s6 * OUT_DIM + c4);
        float4 v7 = *(const float4*)(g_hp + (size_t)s7 * OUT_DIM + c4);
        acc.x += (v0.x + v1.x) + (v2.x + v3.x) + (v4.x + v5.x) + (v6.x + v7.x);
        acc.y += (v0.y + v1.y) + (v2.y + v3.y) + (v4.y + v5.y) + (v6.y + v7.y);
        acc.z += (v0.z + v1.z) + (v2.z + v3.z) + (v4.z + v5.z) + (v6.z + v7.z);
        acc.w += (v0.w + v1.w) + (v2.w + v3.w) + (v4.w + v5.w) + (v6.w + v7.w);
    }
    for (; e < deg; e++) {
        int s = __ldg(adj + e);
        float4 v = *(const float4*)(g_hp + (size_t)s * OUT_DIM + c4);
        acc.x += v.x; acc.y += v.y; acc.z += v.z; acc.w += v.w;
    }

    float4 bb = *(const float4*)(b + c4);
    acc.x = fmaxf(acc.x + bb.x, 0.f);
    acc.y = fmaxf(acc.y + bb.y, 0.f);
    acc.z = fmaxf(acc.z + bb.z, 0.f);
    acc.w = fmaxf(acc.w + bb.w, 0.f);
    *(float4*)(out + (size_t)node * OUT_DIM + c4) = acc;
}

// ---------------------------------------------------------------------------
// Launch
// inputs: 0=h [N,128] f32, 1=W [4,128,64] f32, 2=b [64] f32,
//         3=src [E] i32, 4=dst [E] i32 ; out: [N,64] f32
// ---------------------------------------------------------------------------
extern "C" void kernel_launch(void* const* d_in, const int* in_sizes, int n_in,
                              void* d_out, int out_size) {
    const float* h   = (const float*)d_in[0];
    const float* W   = (const float*)d_in[1];
    const float* b   = (const float*)d_in[2];
    const int*   src = (const int*)d_in[3];
    const int*   dst = (const int*)d_in[4];
    float* out = (float*)d_out;

    int n_nodes = in_sizes[0] / IN_DIM;    // 50000
    int n_edges = in_sizes[3];             // 800000

    // 1. setup: Wavg tf32 split + zero deg
    setup_kernel<<<64, 256>>>(W, n_nodes);

    // 2. fused GEMM + adjacency build
    {
        int n_gemm = (n_nodes + BM - 1) / BM;                 // 391
        int nGroups = n_edges / 4 + 1;                        // 200001
        int n_adj = (nGroups + 255) / 256;                    // 782
        int grid = 3 * n_gemm;                                // 391 gemm, 782 adj
        if (grid - n_gemm < n_adj) grid = n_gemm + n_adj + (n_gemm + n_adj) / 2 + 2;
        fused_kernel<<<grid, 256>>>(h, src, dst, n_nodes, n_edges, n_gemm);
    }

    // 3. pull-aggregate + bias + relu
    {
        long long threads = (long long)n_nodes * 16;
        int blocks = (int)((threads + 255) / 256);
        pull_kernel<<<blocks, 256>>>(b, out, n_nodes);
    }
}

// round 14
// speedup vs baseline: 1.6625x; 1.1966x over previous
#include <cuda_runtime.h>
#include <cuda_fp16.h>
#include <cstdint>

#define N_NODES 50000
#define N_EDGES 800000
#define IN_DIM 128
#define OUT_DIM 64
#define NUM_HEADS 4
#define MAXDEG 96

// Scratch (no cudaMalloc allowed)
__device__ float  g_Whi[IN_DIM * OUT_DIM];           // tf32-rounded hi part of Wavg
__device__ float  g_Wlo[IN_DIM * OUT_DIM];           // tf32-rounded residual
__device__ __half g_hph[N_NODES * OUT_DIM];          // 6.4 MB projected features (fp16)
__device__ int    g_deg[N_NODES];                    // 200 KB
__device__ int    g_adj[(size_t)N_NODES * MAXDEG];   // 19.2 MB

// ---------------------------------------------------------------------------
// tf32 helpers
// ---------------------------------------------------------------------------
__device__ __forceinline__ void split_tf32(float x, uint32_t& hi, uint32_t& lo) {
    asm("cvt.rna.tf32.f32 %0, %1;" : "=r"(hi) : "f"(x));
    float r = x - __uint_as_float(hi);
    asm("cvt.rna.tf32.f32 %0, %1;" : "=r"(lo) : "f"(r));
}

#define MMA_TF32(D, A0, A1, A2, A3, B0, B1)                                    \
    asm("mma.sync.aligned.m16n8k8.row.col.f32.tf32.tf32.f32 "                  \
        "{%0,%1,%2,%3}, {%4,%5,%6,%7}, {%8,%9}, {%0,%1,%2,%3};"                \
        : "+f"((D)[0]), "+f"((D)[1]), "+f"((D)[2]), "+f"((D)[3])               \
        : "r"(A0), "r"(A1), "r"(A2), "r"(A3), "r"(B0), "r"(B1))

// ---------------------------------------------------------------------------
// Kernel 1: setup — Wavg tf32 hi/lo split + zero degree counters
// ---------------------------------------------------------------------------
__global__ void setup_kernel(const float* __restrict__ W, int n_nodes) {
    int i = blockIdx.x * blockDim.x + threadIdx.x;
    if (i < IN_DIM * OUT_DIM) {
        float avg = 0.25f * (W[i] + W[IN_DIM * OUT_DIM + i] +
                             W[2 * IN_DIM * OUT_DIM + i] + W[3 * IN_DIM * OUT_DIM + i]);
        uint32_t hi, lo;
        split_tf32(avg, hi, lo);
        g_Whi[i] = __uint_as_float(hi);
        g_Wlo[i] = __uint_as_float(lo);
    }
    // zero deg (grid-stride over int4)
    int n4 = n_nodes >> 2;
    for (int j = i; j < n4; j += gridDim.x * blockDim.x)
        ((int4*)g_deg)[j] = make_int4(0, 0, 0, 0);
    if (i < (n_nodes & 3)) g_deg[n4 * 4 + i] = 0;
}

// ---------------------------------------------------------------------------
// Kernel 2: FUSED heterogeneous kernel (R11 config, fp16 epilogue).
//   bid % 3 == 0  -> GEMM tile (hp = h @ Wavg via 3xTF32 mma)   [391 blocks]
//   otherwise     -> adjacency-build chunk (4 edges/thread)      [782 blocks]
// ---------------------------------------------------------------------------
#define BM 128
#define KPH 64
#define PA 68     // sA pitch in floats -> fragment bank = (4*gID + tig) % 32, all distinct

__global__ __launch_bounds__(256) void fused_kernel(const float* __restrict__ h,
                                                    const int* __restrict__ src,
                                                    const int* __restrict__ dst,
                                                    int n_nodes, int n_edges,
                                                    int n_gemm_blocks) {
    __shared__ float sA[BM * PA];    // ~34.8 KB (used by GEMM role)

    int bid = blockIdx.x;
    int tid = threadIdx.x;

    if (bid % 3 != 0 || bid / 3 >= n_gemm_blocks) {
        // ---------------- adjacency role ----------------
        int adjId = bid - bid / 3 - 1;
        if (bid % 3 == 0) adjId = bid;
        int g = adjId * 256 + tid;               // edge group (4 edges)
        int nG = n_edges >> 2;
        if (g < nG) {
            int4 s = ((const int4*)src)[g];
            int4 d = ((const int4*)dst)[g];
            int p0 = atomicAdd(&g_deg[d.x], 1);
            int p1 = atomicAdd(&g_deg[d.y], 1);
            int p2 = atomicAdd(&g_deg[d.z], 1);
            int p3 = atomicAdd(&g_deg[d.w], 1);
            if (p0 < MAXDEG) g_adj[(size_t)d.x * MAXDEG + p0] = s.x;
            if (p1 < MAXDEG) g_adj[(size_t)d.y * MAXDEG + p1] = s.y;
            if (p2 < MAXDEG) g_adj[(size_t)d.z * MAXDEG + p2] = s.z;
            if (p3 < MAXDEG) g_adj[(size_t)d.w * MAXDEG + p3] = s.w;
        } else if (g == nG) {
            for (int e = nG * 4; e < n_edges; e++) {
                int d = dst[e];
                int pos = atomicAdd(&g_deg[d], 1);
                if (pos < MAXDEG) g_adj[(size_t)d * MAXDEG + pos] = src[e];
            }
        }
        return;
    }

    // ---------------- GEMM role ----------------
    int tile = bid / 3;
    int lane = tid & 31;
    int wid  = tid >> 5;       // 0..7
    int wm   = wid & 3;        // M strip: rows wm*32..wm*32+31
    int wn   = wid >> 2;       // N strip: cols wn*32..wn*32+31
    int gID  = lane >> 2;      // 0..7
    int tig  = lane & 3;       // 0..3
    int rowBase = tile * BM;

    float d[2][4][4];          // [mtile][ntile][frag]
    #pragma unroll
    for (int mt = 0; mt < 2; mt++)
        #pragma unroll
        for (int nt = 0; nt < 4; nt++)
            #pragma unroll
            for (int q = 0; q < 4; q++) d[mt][nt][q] = 0.f;

    #pragma unroll
    for (int ph = 0; ph < 2; ph++) {
        // stage h slab: 128 rows x 64 floats = 2048 float4, 8 per thread
        #pragma unroll
        for (int it = 0; it < 8; it++) {
            int item = tid + it * 256;
            int r = item >> 4;          // 16 float4 per row
            int c = item & 15;
            int row = rowBase + r;
            float4 v = make_float4(0.f, 0.f, 0.f, 0.f);
            if (row < n_nodes)
                v = ((const float4*)(h + (size_t)row * IN_DIM + ph * KPH))[c];
            *(float4*)(sA + r * PA + 4 * c) = v;
        }
        __syncthreads();

        #pragma unroll
        for (int kk = 0; kk < KPH; kk += 8) {
            int kg = ph * KPH + kk + tig;    // global k of b0 row

            // B fragments hi/lo for 4 n-tiles (L1-resident __ldg)
            uint32_t bhi[4][2], blo[4][2];
            #pragma unroll
            for (int nt = 0; nt < 4; nt++) {
                int ncol = wn * 32 + nt * 8 + gID;
                int i0 = kg * OUT_DIM + ncol;
                int i1 = (kg + 4) * OUT_DIM + ncol;
                bhi[nt][0] = __float_as_uint(__ldg(g_Whi + i0));
                bhi[nt][1] = __float_as_uint(__ldg(g_Whi + i1));
                blo[nt][0] = __float_as_uint(__ldg(g_Wlo + i0));
                blo[nt][1] = __float_as_uint(__ldg(g_Wlo + i1));
            }

            #pragma unroll
            for (int mt = 0; mt < 2; mt++) {
                const float* ab = sA + (wm * 32 + mt * 16 + gID) * PA + kk + tig;
                float a0 = ab[0];
                float a1 = ab[8 * PA];
                float a2 = ab[4];
                float a3 = ab[8 * PA + 4];
                uint32_t ah[4], al[4];
                split_tf32(a0, ah[0], al[0]);
                split_tf32(a1, ah[1], al[1]);
                split_tf32(a2, ah[2], al[2]);
                split_tf32(a3, ah[3], al[3]);

                #pragma unroll
                for (int nt = 0; nt < 4; nt++) {
                    MMA_TF32(d[mt][nt], ah[0], ah[1], ah[2], ah[3],
                             bhi[nt][0], bhi[nt][1]);
                    MMA_TF32(d[mt][nt], al[0], al[1], al[2], al[3],
                             bhi[nt][0], bhi[nt][1]);
                    MMA_TF32(d[mt][nt], ah[0], ah[1], ah[2], ah[3],
                             blo[nt][0], blo[nt][1]);
                }
            }
        }
        __syncthreads();
    }

    // epilogue: fp16 stores
    #pragma unroll
    for (int mt = 0; mt < 2; mt++) {
        int r0 = rowBase + wm * 32 + mt * 16 + gID;
        #pragma unroll
        for (int nt = 0; nt < 4; nt++) {
            int col = wn * 32 + nt * 8 + tig * 2;
            if (r0 < n_nodes)
                *(__half2*)(g_hph + (size_t)r0 * OUT_DIM + col) =
                    __floats2half2_rn(d[mt][nt][0], d[mt][nt][1]);
            if (r0 + 8 < n_nodes)
                *(__half2*)(g_hph + (size_t)(r0 + 8) * OUT_DIM + col) =
                    __floats2half2_rn(d[mt][nt][2], d[mt][nt][3]);
        }
    }
}

// ---------------------------------------------------------------------------
// Kernel 3: pull-aggregate + bias + relu.
// fp16 gathers; 2-level HADD2 tree (combine 4 edges in half) then fp32
// accumulation -> conversion count /4 vs naive, error ~ storage-level.
// ---------------------------------------------------------------------------
__global__ __launch_bounds__(256) void pull_kernel(const float* __restrict__ b,
                                                   float* __restrict__ out,
                                                   int n_nodes) {
    unsigned int t = blockIdx.x * blockDim.x + threadIdx.x;
    unsigned int node = t >> 4;
    if (node >= (unsigned int)n_nodes) return;
    int c4 = (t & 15) * 4;    // half-column offset

    int deg = g_deg[node];
    if (deg > MAXDEG) deg = MAXDEG;
    const int* adj = g_adj + (size_t)node * MAXDEG;

    float2 accA = make_float2(0.f, 0.f);
    float2 accB = make_float2(0.f, 0.f);

    int e = 0;
    for (; e + 8 <= deg; e += 8) {
        int s0 = __ldg(adj + e + 0);
        int s1 = __ldg(adj + e + 1);
        int s2 = __ldg(adj + e + 2);
        int s3 = __ldg(adj + e + 3);
        int s4 = __ldg(adj + e + 4);
        int s5 = __ldg(adj + e + 5);
        int s6 = __ldg(adj + e + 6);
        int s7 = __ldg(adj + e + 7);
        uint2 u0 = *(const uint2*)(g_hph + (size_t)s0 * OUT_DIM + c4);
        uint2 u1 = *(const uint2*)(g_hph + (size_t)s1 * OUT_DIM + c4);
        uint2 u2 = *(const uint2*)(g_hph + (size_t)s2 * OUT_DIM + c4);
        uint2 u3 = *(const uint2*)(g_hph + (size_t)s3 * OUT_DIM + c4);
        uint2 u4 = *(const uint2*)(g_hph + (size_t)s4 * OUT_DIM + c4);
        uint2 u5 = *(const uint2*)(g_hph + (size_t)s5 * OUT_DIM + c4);
        uint2 u6 = *(const uint2*)(g_hph + (size_t)s6 * OUT_DIM + c4);
        uint2 u7 = *(const uint2*)(g_hph + (size_t)s7 * OUT_DIM + c4);
        // 2-level HADD2 tree per 4 edges, then convert + fp32 add
        __half2 a01 = __hadd2(*(__half2*)&u0.x, *(__half2*)&u1.x);
        __half2 a23 = __hadd2(*(__half2*)&u2.x, *(__half2*)&u3.x);
        __half2 a45 = __hadd2(*(__half2*)&u4.x, *(__half2*)&u5.x);
        __half2 a67 = __hadd2(*(__half2*)&u6.x, *(__half2*)&u7.x);
        __half2 b01 = __hadd2(*(__half2*)&u0.y, *(__half2*)&u1.y);
        __half2 b23 = __hadd2(*(__half2*)&u2.y, *(__half2*)&u3.y);
        __half2 b45 = __hadd2(*(__half2*)&u4.y, *(__half2*)&u5.y);
        __half2 b67 = __hadd2(*(__half2*)&u6.y, *(__half2*)&u7.y);
        __half2 a03 = __hadd2(a01, a23);
        __half2 a47 = __hadd2(a45, a67);
        __half2 b03 = __hadd2(b01, b23);
        __half2 b47 = __hadd2(b45, b67);
        float2 fA0 = __half22float2(a03);
        float2 fA1 = __half22float2(a47);
        float2 fB0 = __half22float2(b03);
        float2 fB1 = __half22float2(b47);
        accA.x += fA0.x + fA1.x;  accA.y += fA0.y + fA1.y;
        accB.x += fB0.x + fB1.x;  accB.y += fB0.y + fB1.y;
    }
    for (; e < deg; e++) {
        int s = __ldg(adj + e);
        uint2 u = *(const uint2*)(g_hph + (size_t)s * OUT_DIM + c4);
        float2 f0 = __half22float2(*(__half2*)&u.x);
        float2 f1 = __half22float2(*(__half2*)&u.y);
        accA.x += f0.x; accA.y += f0.y;
        accB.x += f1.x; accB.y += f1.y;
    }

    float4 bb = *(const float4*)(b + c4);
    float4 r;
    r.x = fmaxf(accA.x + bb.x, 0.f);
    r.y = fmaxf(accA.y + bb.y, 0.f);
    r.z = fmaxf(accB.x + bb.z, 0.f);
    r.w = fmaxf(accB.y + bb.w, 0.f);
    *(float4*)(out + (size_t)node * OUT_DIM + c4) = r;
}

// ---------------------------------------------------------------------------
// Launch
// inputs: 0=h [N,128] f32, 1=W [4,128,64] f32, 2=b [64] f32,
//         3=src [E] i32, 4=dst [E] i32 ; out: [N,64] f32
// ---------------------------------------------------------------------------
extern "C" void kernel_launch(void* const* d_in, const int* in_sizes, int n_in,
                              void* d_out, int out_size) {
    const float* h   = (const float*)d_in[0];
    const float* W   = (const float*)d_in[1];
    const float* b   = (const float*)d_in[2];
    const int*   src = (const int*)d_in[3];
    const int*   dst = (const int*)d_in[4];
    float* out = (float*)d_out;

    int n_nodes = in_sizes[0] / IN_DIM;    // 50000
    int n_edges = in_sizes[3];             // 800000

    // 1. setup: Wavg tf32 split + zero deg
    setup_kernel<<<64, 256>>>(W, n_nodes);

    // 2. fused GEMM + adjacency build
    {
        int n_gemm = (n_nodes + BM - 1) / BM;                 // 391
        int nGroups = n_edges / 4 + 1;                        // 200001
        int n_adj = (nGroups + 255) / 256;                    // 782
        int grid = 3 * n_gemm;                                // 391 gemm, 782 adj
        if (grid - n_gemm < n_adj) grid = n_gemm + n_adj + (n_gemm + n_adj) / 2 + 2;
        fused_kernel<<<grid, 256>>>(h, src, dst, n_nodes, n_edges, n_gemm);
    }

    // 3. pull-aggregate + bias + relu
    {
        long long threads = (long long)n_nodes * 16;
        int blocks = (int)((threads + 255) / 256);
        pull_kernel<<<blocks, 256>>>(b, out, n_nodes);
    }
}

// round 15
// speedup vs baseline: 1.9279x; 1.1596x over previous
#include <cuda_runtime.h>
#include <cuda_fp16.h>
#include <cuda_bf16.h>
#include <cstdint>

#define N_NODES 50000
#define N_EDGES 800000
#define IN_DIM 128
#define OUT_DIM 64
#define NUM_HEADS 4
#define MAXDEG 96

// Scratch (no cudaMalloc allowed)
__device__ uint32_t g_Wbh[(IN_DIM / 2) * OUT_DIM];   // packed bf16x2 hi pairs (k,k+1)
__device__ uint32_t g_Wbl[(IN_DIM / 2) * OUT_DIM];   // packed bf16x2 lo (residual) pairs
__device__ __half   g_hph[N_NODES * OUT_DIM];        // 6.4 MB projected features (fp16)
__device__ int      g_deg[N_NODES];                  // 200 KB
__device__ int      g_adj[(size_t)N_NODES * MAXDEG]; // 19.2 MB

// ---------------------------------------------------------------------------
// bf16 helpers
// ---------------------------------------------------------------------------
__device__ __forceinline__ uint32_t pack_bf16(float a, float b) {
    __nv_bfloat162 t = __floats2bfloat162_rn(a, b);   // low half = a (even k)
    return *(uint32_t*)&t;
}
__device__ __forceinline__ float bf16_hi(float x) {
    return __bfloat162float(__float2bfloat16_rn(x));
}

#define MMA_BF16(D, A0, A1, A2, A3, B0, B1)                                    \
    asm("mma.sync.aligned.m16n8k16.row.col.f32.bf16.bf16.f32 "                 \
        "{%0,%1,%2,%3}, {%4,%5,%6,%7}, {%8,%9}, {%0,%1,%2,%3};"                \
        : "+f"((D)[0]), "+f"((D)[1]), "+f"((D)[2]), "+f"((D)[3])               \
        : "r"(A0), "r"(A1), "r"(A2), "r"(A3), "r"(B0), "r"(B1))

// ---------------------------------------------------------------------------
// Kernel 1: setup — Wavg 2-term bf16 split into packed k-pairs + zero deg.
// Thread i handles pair p = i>>6 (k = 2p, 2p+1), column n = i&63.
// ---------------------------------------------------------------------------
__global__ void setup_kernel(const float* __restrict__ W, int n_nodes) {
    int i = blockIdx.x * blockDim.x + threadIdx.x;
    if (i < (IN_DIM / 2) * OUT_DIM) {
        int p = i >> 6;
        int n = i & 63;
        float a0 = 0.f, a1 = 0.f;
        #pragma unroll
        for (int hd = 0; hd < NUM_HEADS; hd++) {
            a0 += W[hd * IN_DIM * OUT_DIM + (2 * p) * OUT_DIM + n];
            a1 += W[hd * IN_DIM * OUT_DIM + (2 * p + 1) * OUT_DIM + n];
        }
        a0 *= 0.25f; a1 *= 0.25f;
        float h0 = bf16_hi(a0), h1 = bf16_hi(a1);
        g_Wbh[i] = pack_bf16(h0, h1);
        g_Wbl[i] = pack_bf16(a0 - h0, a1 - h1);
    }
    // zero deg (grid-stride over int4)
    int n4 = n_nodes >> 2;
    for (int j = i; j < n4; j += gridDim.x * blockDim.x)
        ((int4*)g_deg)[j] = make_int4(0, 0, 0, 0);
    if (i < (n_nodes & 3)) g_deg[n4 * 4 + i] = 0;
}

// ---------------------------------------------------------------------------
// Kernel 2: FUSED heterogeneous kernel.
//   bid % 3 == 0  -> GEMM tile via mma.m16n8k16.bf16, 3-term bf16 split
//   otherwise     -> adjacency-build chunk (4 edges/thread)
// A pre-split into packed bf16x2 hi/lo planes at staging (no cvt in hot loop).
// ---------------------------------------------------------------------------
#define BM 128
#define KPH 64
#define PPITCH 36   // sA pitch in PAIRS -> fragment bank = (4*gID + tig) % 32, distinct

__global__ __launch_bounds__(256) void fused_kernel(const float* __restrict__ h,
                                                    const int* __restrict__ src,
                                                    const int* __restrict__ dst,
                                                    int n_nodes, int n_edges,
                                                    int n_gemm_blocks) {
    __shared__ uint32_t sAh[BM * PPITCH];   // 18 KB packed bf16x2 hi pairs
    __shared__ uint32_t sAl[BM * PPITCH];   // 18 KB packed bf16x2 lo pairs

    int bid = blockIdx.x;
    int tid = threadIdx.x;

    if (bid % 3 != 0 || bid / 3 >= n_gemm_blocks) {
        // ---------------- adjacency role ----------------
        int adjId = bid - bid / 3 - 1;
        if (bid % 3 == 0) adjId = bid;
        int g = adjId * 256 + tid;               // edge group (4 edges)
        int nG = n_edges >> 2;
        if (g < nG) {
            int4 s = ((const int4*)src)[g];
            int4 d = ((const int4*)dst)[g];
            int p0 = atomicAdd(&g_deg[d.x], 1);
            int p1 = atomicAdd(&g_deg[d.y], 1);
            int p2 = atomicAdd(&g_deg[d.z], 1);
            int p3 = atomicAdd(&g_deg[d.w], 1);
            if (p0 < MAXDEG) g_adj[(size_t)d.x * MAXDEG + p0] = s.x;
            if (p1 < MAXDEG) g_adj[(size_t)d.y * MAXDEG + p1] = s.y;
            if (p2 < MAXDEG) g_adj[(size_t)d.z * MAXDEG + p2] = s.z;
            if (p3 < MAXDEG) g_adj[(size_t)d.w * MAXDEG + p3] = s.w;
        } else if (g == nG) {
            for (int e = nG * 4; e < n_edges; e++) {
                int d = dst[e];
                int pos = atomicAdd(&g_deg[d], 1);
                if (pos < MAXDEG) g_adj[(size_t)d * MAXDEG + pos] = src[e];
            }
        }
        return;
    }

    // ---------------- GEMM role ----------------
    int tile = bid / 3;
    int lane = tid & 31;
    int wid  = tid >> 5;       // 0..7
    int wm   = wid & 3;        // M strip: rows wm*32..wm*32+31
    int wn   = wid >> 2;       // N strip: cols wn*32..wn*32+31
    int gID  = lane >> 2;      // 0..7
    int tig  = lane & 3;       // 0..3
    int rowBase = tile * BM;

    float d[2][4][4];          // [mtile][ntile][frag]
    #pragma unroll
    for (int mt = 0; mt < 2; mt++)
        #pragma unroll
        for (int nt = 0; nt < 4; nt++)
            #pragma unroll
            for (int q = 0; q < 4; q++) d[mt][nt][q] = 0.f;

    #pragma unroll
    for (int ph = 0; ph < 2; ph++) {
        // stage h slab pre-split: 128 rows x 64 floats = 2048 float4, 8/thread.
        // float4 covers k = 4c..4c+3 -> local pairs 2c (k,k+1) and 2c+1 (k+2,k+3)
        #pragma unroll
        for (int it = 0; it < 8; it++) {
            int item = tid + it * 256;
            int r = item >> 4;          // 16 float4 per row
            int c = item & 15;
            int row = rowBase + r;
            float4 v = make_float4(0.f, 0.f, 0.f, 0.f);
            if (row < n_nodes)
                v = ((const float4*)(h + (size_t)row * IN_DIM + ph * KPH))[c];
            float hx = bf16_hi(v.x), hy = bf16_hi(v.y);
            float hz = bf16_hi(v.z), hw = bf16_hi(v.w);
            int base = r * PPITCH + 2 * c;
            sAh[base]     = pack_bf16(hx, hy);
            sAh[base + 1] = pack_bf16(hz, hw);
            sAl[base]     = pack_bf16(v.x - hx, v.y - hy);
            sAl[base + 1] = pack_bf16(v.z - hz, v.w - hw);
        }
        __syncthreads();

        #pragma unroll
        for (int ksl = 0; ksl < KPH / 16; ksl++) {          // 4 k16-steps per phase
            int kstep = ph * (KPH / 16) + ksl;              // global k16-step 0..7
            int p0 = kstep * 8 + tig;                       // W pair row of b0

            // B fragments hi/lo for 4 n-tiles
            uint32_t bh[4][2], bl[4][2];
            #pragma unroll
            for (int nt = 0; nt < 4; nt++) {
                int ncol = wn * 32 + nt * 8 + gID;
                bh[nt][0] = __ldg(g_Wbh + p0 * OUT_DIM + ncol);
                bh[nt][1] = __ldg(g_Wbh + (p0 + 4) * OUT_DIM + ncol);
                bl[nt][0] = __ldg(g_Wbl + p0 * OUT_DIM + ncol);
                bl[nt][1] = __ldg(g_Wbl + (p0 + 4) * OUT_DIM + ncol);
            }

            #pragma unroll
            for (int mt = 0; mt < 2; mt++) {
                int row = wm * 32 + mt * 16 + gID;
                int q = ksl * 8 + tig;                      // local pair index
                uint32_t ah0 = sAh[row * PPITCH + q];
                uint32_t ah1 = sAh[(row + 8) * PPITCH + q];
                uint32_t ah2 = sAh[row * PPITCH + q + 4];
                uint32_t ah3 = sAh[(row + 8) * PPITCH + q + 4];
                uint32_t al0 = sAl[row * PPITCH + q];
                uint32_t al1 = sAl[(row + 8) * PPITCH + q];
                uint32_t al2 = sAl[row * PPITCH + q + 4];
                uint32_t al3 = sAl[(row + 8) * PPITCH + q + 4];

                #pragma unroll
                for (int nt = 0; nt < 4; nt++) {
                    MMA_BF16(d[mt][nt], ah0, ah1, ah2, ah3, bh[nt][0], bh[nt][1]);
                    MMA_BF16(d[mt][nt], al0, al1, al2, al3, bh[nt][0], bh[nt][1]);
                    MMA_BF16(d[mt][nt], ah0, ah1, ah2, ah3, bl[nt][0], bl[nt][1]);
                }
            }
        }
        __syncthreads();
    }

    // epilogue: fp16 stores (D layout of m16n8k16 == m16n8k8)
    #pragma unroll
    for (int mt = 0; mt < 2; mt++) {
        int r0 = rowBase + wm * 32 + mt * 16 + gID;
        #pragma unroll
        for (int nt = 0; nt < 4; nt++) {
            int col = wn * 32 + nt * 8 + tig * 2;
            if (r0 < n_nodes)
                *(__half2*)(g_hph + (size_t)r0 * OUT_DIM + col) =
                    __floats2half2_rn(d[mt][nt][0], d[mt][nt][1]);
            if (r0 + 8 < n_nodes)
                *(__half2*)(g_hph + (size_t)(r0 + 8) * OUT_DIM + col) =
                    __floats2half2_rn(d[mt][nt][2], d[mt][nt][3]);
        }
    }
}

// ---------------------------------------------------------------------------
// Kernel 3: pull-aggregate + bias + relu (R14 winner, unchanged).
// ---------------------------------------------------------------------------
__global__ __launch_bounds__(256) void pull_kernel(const float* __restrict__ b,
                                                   float* __restrict__ out,
                                                   int n_nodes) {
    unsigned int t = blockIdx.x * blockDim.x + threadIdx.x;
    unsigned int node = t >> 4;
    if (node >= (unsigned int)n_nodes) return;
    int c4 = (t & 15) * 4;    // half-column offset

    int deg = g_deg[node];
    if (deg > MAXDEG) deg = MAXDEG;
    const int* adj = g_adj + (size_t)node * MAXDEG;

    float2 accA = make_float2(0.f, 0.f);
    float2 accB = make_float2(0.f, 0.f);

    int e = 0;
    for (; e + 8 <= deg; e += 8) {
        int s0 = __ldg(adj + e + 0);
        int s1 = __ldg(adj + e + 1);
        int s2 = __ldg(adj + e + 2);
        int s3 = __ldg(adj + e + 3);
        int s4 = __ldg(adj + e + 4);
        int s5 = __ldg(adj + e + 5);
        int s6 = __ldg(adj + e + 6);
        int s7 = __ldg(adj + e + 7);
        uint2 u0 = *(const uint2*)(g_hph + (size_t)s0 * OUT_DIM + c4);
        uint2 u1 = *(const uint2*)(g_hph + (size_t)s1 * OUT_DIM + c4);
        uint2 u2 = *(const uint2*)(g_hph + (size_t)s2 * OUT_DIM + c4);
        uint2 u3 = *(const uint2*)(g_hph + (size_t)s3 * OUT_DIM + c4);
        uint2 u4 = *(const uint2*)(g_hph + (size_t)s4 * OUT_DIM + c4);
        uint2 u5 = *(const uint2*)(g_hph + (size_t)s5 * OUT_DIM + c4);
        uint2 u6 = *(const uint2*)(g_hph + (size_t)s6 * OUT_DIM + c4);
        uint2 u7 = *(const uint2*)(g_hph + (size_t)s7 * OUT_DIM + c4);
        __half2 a01 = __hadd2(*(__half2*)&u0.x, *(__half2*)&u1.x);
        __half2 a23 = __hadd2(*(__half2*)&u2.x, *(__half2*)&u3.x);
        __half2 a45 = __hadd2(*(__half2*)&u4.x, *(__half2*)&u5.x);
        __half2 a67 = __hadd2(*(__half2*)&u6.x, *(__half2*)&u7.x);
        __half2 b01 = __hadd2(*(__half2*)&u0.y, *(__half2*)&u1.y);
        __half2 b23 = __hadd2(*(__half2*)&u2.y, *(__half2*)&u3.y);
        __half2 b45 = __hadd2(*(__half2*)&u4.y, *(__half2*)&u5.y);
        __half2 b67 = __hadd2(*(__half2*)&u6.y, *(__half2*)&u7.y);
        __half2 a03 = __hadd2(a01, a23);
        __half2 a47 = __hadd2(a45, a67);
        __half2 b03 = __hadd2(b01, b23);
        __half2 b47 = __hadd2(b45, b67);
        float2 fA0 = __half22float2(a03);
        float2 fA1 = __half22float2(a47);
        float2 fB0 = __half22float2(b03);
        float2 fB1 = __half22float2(b47);
        accA.x += fA0.x + fA1.x;  accA.y += fA0.y + fA1.y;
        accB.x += fB0.x + fB1.x;  accB.y += fB0.y + fB1.y;
    }
    for (; e < deg; e++) {
        int s = __ldg(adj + e);
        uint2 u = *(const uint2*)(g_hph + (size_t)s * OUT_DIM + c4);
        float2 f0 = __half22float2(*(__half2*)&u.x);
        float2 f1 = __half22float2(*(__half2*)&u.y);
        accA.x += f0.x; accA.y += f0.y;
        accB.x += f1.x; accB.y += f1.y;
    }

    float4 bb = *(const float4*)(b + c4);
    float4 r;
    r.x = fmaxf(accA.x + bb.x, 0.f);
    r.y = fmaxf(accA.y + bb.y, 0.f);
    r.z = fmaxf(accB.x + bb.z, 0.f);
    r.w = fmaxf(accB.y + bb.w, 0.f);
    *(float4*)(out + (size_t)node * OUT_DIM + c4) = r;
}

// ---------------------------------------------------------------------------
// Launch
// inputs: 0=h [N,128] f32, 1=W [4,128,64] f32, 2=b [64] f32,
//         3=src [E] i32, 4=dst [E] i32 ; out: [N,64] f32
// ---------------------------------------------------------------------------
extern "C" void kernel_launch(void* const* d_in, const int* in_sizes, int n_in,
                              void* d_out, int out_size) {
    const float* h   = (const float*)d_in[0];
    const float* W   = (const float*)d_in[1];
    const float* b   = (const float*)d_in[2];
    const int*   src = (const int*)d_in[3];
    const int*   dst = (const int*)d_in[4];
    float* out = (float*)d_out;

    int n_nodes = in_sizes[0] / IN_DIM;    // 50000
    int n_edges = in_sizes[3];             // 800000

    // 1. setup: Wavg bf16 split + zero deg
    setup_kernel<<<64, 256>>>(W, n_nodes);

    // 2. fused GEMM + adjacency build
    {
        int n_gemm = (n_nodes + BM - 1) / BM;                 // 391
        int nGroups = n_edges / 4 + 1;                        // 200001
        int n_adj = (nGroups + 255) / 256;                    // 782
        int grid = 3 * n_gemm;                                // 391 gemm, 782 adj
        if (grid - n_gemm < n_adj) grid = n_gemm + n_adj + (n_gemm + n_adj) / 2 + 2;
        fused_kernel<<<grid, 256>>>(h, src, dst, n_nodes, n_edges, n_gemm);
    }

    // 3. pull-aggregate + bias + relu
    {
        long long threads = (long long)n_nodes * 16;
        int blocks = (int)((threads + 255) / 256);
        pull_kernel<<<blocks, 256>>>(b, out, n_nodes);
    }
}